// round 2
// baseline (speedup 1.0000x reference)
#include <cuda_runtime.h>

#define NN 1024
#define TOPK 16
#define NPAIR 272           // 256 pos (c_hi,t) pairs + 16 rep c_hi slices
#define KDIM (NPAIR * 32)   // 8704

// Scratch (device globals: allocation-free per harness rules)
__device__ int   g_idx[NN * TOPK];       // top-16 indices per row
__device__ int   g_row[NPAIR * 64];      // gathered f1 row per (pair, b)
__device__ float g_B[KDIM * NN];         // permuted/reduced weights [K, 1024]

// ---------------------------------------------------------------------------
// Kernel 1: exact top-16 per row (descending, ties -> lowest index)
// ---------------------------------------------------------------------------
__global__ void topk_kernel(const float* __restrict__ f1) {
    __shared__ float sv[NN];
    __shared__ float rv[256];
    __shared__ int   ri[256];
    const int n = blockIdx.x, tid = threadIdx.x;
    for (int i = tid; i < NN; i += 256) sv[i] = f1[n * NN + i];
    __syncthreads();
    const float NEG_INF = __int_as_float(0xff800000);
    for (int it = 0; it < TOPK; ++it) {
        float best = NEG_INF;
        int bi = 0;
        for (int i = tid; i < NN; i += 256) {
            float v = sv[i];
            if (v > best) { best = v; bi = i; }   // strictly greater -> keeps lowest idx
        }
        rv[tid] = best; ri[tid] = bi;
        __syncthreads();
        for (int s = 128; s > 0; s >>= 1) {
            if (tid < s) {
                float ov = rv[tid + s]; int oi = ri[tid + s];
                if (ov > rv[tid] || (ov == rv[tid] && oi < ri[tid])) {
                    rv[tid] = ov; ri[tid] = oi;
                }
            }
            __syncthreads();
        }
        if (tid == 0) { g_idx[n * TOPK + it] = ri[0]; sv[ri[0]] = NEG_INF; }
        __syncthreads();
    }
}

// ---------------------------------------------------------------------------
// Kernel 2: row-index table. pair<256: (c_hi=pair>>4, t=pair&15) -> idx row.
//           pair>=256: rep slice -> own row b*16 + c_hi.
// ---------------------------------------------------------------------------
__global__ void rows_kernel() {
    int i = blockIdx.x * blockDim.x + threadIdx.x;
    if (i >= NPAIR * 64) return;
    int pair = i >> 6, b = i & 63;
    int r;
    if (pair < 256) {
        int c_hi = pair >> 4, t = pair & 15;
        r = g_idx[(b * TOPK + c_hi) * TOPK + t];
    } else {
        r = b * TOPK + (pair - 256);
    }
    g_row[i] = r;
}

// ---------------------------------------------------------------------------
// Kernel 3: build permuted weights g_B[(pair*32 + c2*16 + h) * 1024 + o].
//   pos (pair<256):  conv_w[o, c_hi*64 + t*4 + 2 + c2, h]  (32 contiguous floats)
//   rep (pair>=256): sum_t conv_w[o, c_hi*64 + t*4 + c2, h]
// Coalesced reads + smem transpose -> coalesced writes.
// ---------------------------------------------------------------------------
__global__ void build_B_kernel(const float* __restrict__ conv_w) {
    __shared__ float s[32][33];
    const int pair = blockIdx.x;     // 0..271
    const int tid  = threadIdx.x;    // 256
    const int jj = tid & 31;
    const int og = tid >> 5;         // 0..7
    for (int o0 = 0; o0 < NN; o0 += 32) {
        if (pair < 256) {
            int c_hi = pair >> 4, t = pair & 15;
            int base = (c_hi * 64 + t * 4 + 2) * 16;
#pragma unroll
            for (int q = 0; q < 4; ++q) {
                int oo = og * 4 + q;
                s[oo][jj] = conv_w[(o0 + oo) * 16384 + base + jj];
            }
        } else {
            int c_hi = pair - 256;
#pragma unroll
            for (int q = 0; q < 4; ++q) {
                int oo = og * 4 + q;
                const float* p = conv_w + (o0 + oo) * 16384 + c_hi * 1024 + jj;
                float acc = 0.f;
#pragma unroll
                for (int t = 0; t < 16; ++t) acc += p[t * 64];
                s[oo][jj] = acc;
            }
        }
        __syncthreads();
#pragma unroll
        for (int q = 0; q < 4; ++q) {
            int j = og * 4 + q;
            g_B[(pair * 32 + j) * NN + o0 + jj] = s[jj][j];
        }
        __syncthreads();
    }
}

// ---------------------------------------------------------------------------
// Kernel 4: GEMM  C[2048, 1024] = A(gathered f1) @ g_B, fused bias+relu store.
// BM=128 (4 b's x 32 w), BN=128, BK=32 (one pair per K step).
// Packed fp32x2 FMA for full-rate fp32 on sm_103. Register-staged pipeline
// hides gmem latency behind the compute phase.
// ---------------------------------------------------------------------------
__device__ __forceinline__ unsigned long long pack2(float lo, float hi) {
    unsigned long long r;
    asm("mov.b64 %0, {%1, %2};" : "=l"(r) : "f"(lo), "f"(hi));
    return r;
}
__device__ __forceinline__ void fma2(unsigned long long& d,
                                     unsigned long long a, unsigned long long b) {
    asm("fma.rn.f32x2 %0, %1, %2, %0;" : "+l"(d) : "l"(a), "l"(b));
}
__device__ __forceinline__ void unpack2(unsigned long long v, float& lo, float& hi) {
    asm("mov.b64 {%0, %1}, %2;" : "=f"(lo), "=f"(hi) : "l"(v));
}

__global__ __launch_bounds__(256) void gemm_kernel(
    const float* __restrict__ f1, const float* __restrict__ conv_b,
    float* __restrict__ out) {
    __shared__ float As[32][132];   // [k][m], padded
    __shared__ float Bs[32][132];   // [k][n], padded

    const int tid = threadIdx.x;
    const int m0 = blockIdx.y * 128;
    const int n0 = blockIdx.x * 128;
    const int tm = (tid >> 4) * 8;
    const int tn = (tid & 15) * 8;

    // A-load mapping: 4 gathered rows of 1024 floats -> As[k][bl*32 + w]
    const int bl    = tid >> 6;          // which of 4 b's in this tile
    const int l64   = tid & 63;          // 16 floats each
    const int bglob = (m0 >> 5) + bl;    // global b
    // B-load mapping
    const int bk = tid >> 3;             // k row 0..31
    const int bn = (tid & 7) * 4;        // + j*32

    unsigned long long acc[8][4];
#pragma unroll
    for (int i = 0; i < 8; ++i)
#pragma unroll
        for (int j = 0; j < 4; ++j) acc[i][j] = 0ull;

    float4 ra[4], rb[4];

    // ---- fetch: gmem -> regs for a given pair ----
    auto fetch = [&](int pair) {
        int r = g_row[pair * 64 + bglob];
        const float4* src = (const float4*)(f1 + r * NN) + l64 * 4;
#pragma unroll
        for (int q = 0; q < 4; ++q) ra[q] = src[q];
        const float* gb = g_B + (pair * 32 + bk) * NN + n0 + bn;
#pragma unroll
        for (int j = 0; j < 4; ++j) rb[j] = *(const float4*)(gb + j * 32);
    };
    // ---- store: regs -> smem ----
    auto store = [&]() {
#pragma unroll
        for (int q = 0; q < 4; ++q) {
            int l = l64 * 16 + q * 4;                       // l = c2*512 + h*32 + w
            int k = ((l >= 512) ? 16 : 0) + ((l & 511) >> 5);
            int w = l & 31;
            *(float4*)&As[k][bl * 32 + w] = ra[q];
        }
#pragma unroll
        for (int j = 0; j < 4; ++j)
            *(float4*)&Bs[bk][bn + j * 32] = rb[j];
    };

    fetch(0);
    store();
    __syncthreads();

    for (int pair = 0; pair < NPAIR; ++pair) {
        if (pair + 1 < NPAIR) fetch(pair + 1);

        // ---- compute from smem ----
#pragma unroll
        for (int k = 0; k < 32; ++k) {
            float4 a0 = *(const float4*)&As[k][tm];
            float4 a1 = *(const float4*)&As[k][tm + 4];
            float4 b0 = *(const float4*)&Bs[k][tn];
            float4 b1 = *(const float4*)&Bs[k][tn + 4];
            unsigned long long bb[4];
            bb[0] = pack2(b0.x, b0.y); bb[1] = pack2(b0.z, b0.w);
            bb[2] = pack2(b1.x, b1.y); bb[3] = pack2(b1.z, b1.w);
            float av[8] = {a0.x, a0.y, a0.z, a0.w, a1.x, a1.y, a1.z, a1.w};
#pragma unroll
            for (int i = 0; i < 8; ++i) {
                unsigned long long aa = pack2(av[i], av[i]);
#pragma unroll
                for (int j = 0; j < 4; ++j) fma2(acc[i][j], aa, bb[j]);
            }
        }
        __syncthreads();
        if (pair + 1 < NPAIR) {
            store();
            __syncthreads();
        }
    }

    // ---- epilogue: bias + relu, out[b*32768 + o*32 + w] ----
#pragma unroll
    for (int i = 0; i < 8; ++i) {
        int m = m0 + tm + i;
        int b = m >> 5, w = m & 31;
        float* op = out + b * 32768 + w;
#pragma unroll
        for (int j = 0; j < 4; ++j) {
            int o = n0 + tn + 2 * j;
            float lo, hi;
            unpack2(acc[i][j], lo, hi);
            float v0 = lo + conv_b[o];
            float v1 = hi + conv_b[o + 1];
            op[o * 32]       = v0 > 0.f ? v0 : 0.f;
            op[(o + 1) * 32] = v1 > 0.f ? v1 : 0.f;
        }
    }
}

// ---------------------------------------------------------------------------
extern "C" void kernel_launch(void* const* d_in, const int* in_sizes, int n_in,
                              void* d_out, int out_size) {
    const float* f1     = (const float*)d_in[0];   // [1024, 1024]
    const float* conv_w = (const float*)d_in[1];   // [1024, 1024, 16, 1]
    const float* conv_b = (const float*)d_in[2];   // [1024]
    float* out = (float*)d_out;                    // [1024, 2048]

    topk_kernel<<<NN, 256>>>(f1);
    rows_kernel<<<(NPAIR * 64 + 255) / 256, 256>>>();
    build_B_kernel<<<NPAIR, 256>>>(conv_w);
    dim3 grid(NN / 128, 2048 / 128);               // (8, 16) = 128 blocks
    gemm_kernel<<<grid, 256>>>(f1, conv_b, out);
    (void)in_sizes; (void)n_in; (void)out_size;
}

// round 4
// speedup vs baseline: 2.5857x; 2.5857x over previous
#include <cuda_runtime.h>
#include <cuda_bf16.h>
#include <cstdint>

#define NN 1024
#define TOPK 16
#define NPAIR 272           // 256 pos (c_hi,t) pairs + 16 rep c_hi slices
#define KK (NPAIR * 32)     // 8704
#define MM 2048             // (b, w)
#define NCH (KK / 32)       // 272 K-chunks of 32

// Scratch (device globals: allocation-free per harness rules)
__device__ int            g_idx[NN * TOPK];
__device__ int            g_row[NPAIR * 64];
__device__ __nv_bfloat16  g_Ah[(size_t)MM * KK];
__device__ __nv_bfloat16  g_Al[(size_t)MM * KK];
__device__ __nv_bfloat16  g_Bh[(size_t)NN * KK];
__device__ __nv_bfloat16  g_Bl[(size_t)NN * KK];

__device__ __forceinline__ uint32_t smem_u32(const void* p) {
    uint32_t a;
    asm("{ .reg .u64 t; cvta.to.shared.u64 t, %1; cvt.u32.u64 %0, t; }"
        : "=r"(a) : "l"(p));
    return a;
}
__device__ __forceinline__ void split_bf16(float x, __nv_bfloat16& h, __nv_bfloat16& l) {
    h = __float2bfloat16(x);
    l = __float2bfloat16(x - __bfloat162float(h));
}

// ---------------------------------------------------------------------------
// Kernel 1: exact top-16 per row (descending, ties -> lowest index)
// ---------------------------------------------------------------------------
__global__ void topk_kernel(const float* __restrict__ f1) {
    __shared__ float sv[NN];
    __shared__ float rv[256];
    __shared__ int   ri[256];
    const int n = blockIdx.x, tid = threadIdx.x;
    for (int i = tid; i < NN; i += 256) sv[i] = f1[n * NN + i];
    __syncthreads();
    const float NEG_INF = __int_as_float(0xff800000);
    for (int it = 0; it < TOPK; ++it) {
        float best = NEG_INF; int bi = 0;
        for (int i = tid; i < NN; i += 256) {
            float v = sv[i];
            if (v > best) { best = v; bi = i; }
        }
        rv[tid] = best; ri[tid] = bi;
        __syncthreads();
        for (int s = 128; s > 0; s >>= 1) {
            if (tid < s) {
                float ov = rv[tid + s]; int oi = ri[tid + s];
                if (ov > rv[tid] || (ov == rv[tid] && oi < ri[tid])) {
                    rv[tid] = ov; ri[tid] = oi;
                }
            }
            __syncthreads();
        }
        if (tid == 0) { g_idx[n * TOPK + it] = ri[0]; sv[ri[0]] = NEG_INF; }
        __syncthreads();
    }
}

// ---------------------------------------------------------------------------
// Kernel 2: row-index table
// ---------------------------------------------------------------------------
__global__ void rows_kernel() {
    int i = blockIdx.x * blockDim.x + threadIdx.x;
    if (i >= NPAIR * 64) return;
    int pair = i >> 6, b = i & 63;
    int r;
    if (pair < 256) {
        int c_hi = pair >> 4, t = pair & 15;
        r = g_idx[(b * TOPK + c_hi) * TOPK + t];
    } else {
        r = b * TOPK + (pair - 256);
    }
    g_row[i] = r;
}

// ---------------------------------------------------------------------------
// Kernel 3a: build split-bf16 A [MM, KK] K-major.
//   A[b*32+w][pair*32 + c2*16 + h] = f1[g_row[pair,b], c2*512 + h*32 + w]
// ---------------------------------------------------------------------------
__global__ void build_A_kernel(const float* __restrict__ f1) {
    __shared__ float s[1024];
    const int pair = blockIdx.x, b = blockIdx.y, tid = threadIdx.x;
    const int r = g_row[pair * 64 + b];
    for (int i = tid; i < 1024; i += 256) s[i] = f1[r * NN + i];
    __syncthreads();
    const int w  = tid >> 3;
    const int j0 = (tid & 7) * 4;
    const size_t obase = (size_t)(b * 32 + w) * KK + pair * 32;
#pragma unroll
    for (int q = 0; q < 4; ++q) {
        int j = j0 + q;
        float v = s[(j >> 4) * 512 + (j & 15) * 32 + w];
        __nv_bfloat16 h, l; split_bf16(v, h, l);
        g_Ah[obase + j] = h;
        g_Al[obase + j] = l;
    }
}

// ---------------------------------------------------------------------------
// Kernel 3b: build split-bf16 B [NN, KK] K-major.
// ---------------------------------------------------------------------------
__global__ void build_B_kernel(const float* __restrict__ conv_w) {
    const int o = blockIdx.x;
    const float* cw = conv_w + (size_t)o * 16384;
    for (int k = threadIdx.x; k < KK; k += 256) {
        int pair = k >> 5, j = k & 31, c2 = j >> 4, h = j & 15;
        float v;
        if (pair < 256) {
            int ch = pair >> 4, t = pair & 15;
            v = cw[(ch * 64 + t * 4 + 2 + c2) * 16 + h];
        } else {
            int ch = pair - 256;
            v = 0.f;
#pragma unroll
            for (int t = 0; t < 16; ++t) v += cw[(ch * 64 + t * 4 + c2) * 16 + h];
        }
        __nv_bfloat16 hh, ll; split_bf16(v, hh, ll);
        g_Bh[(size_t)o * KK + k] = hh;
        g_Bl[(size_t)o * KK + k] = ll;
    }
}

// ---------------------------------------------------------------------------
// Kernel 4: HMMA GEMM (mma.sync bf16, plain sm_80+ PTX — no 'a' features).
// C[2048,1024] = AhBh + AhBl + AlBh, fused bias+relu.
// CTA tile 128x128, 8 warps (2x4), warp tile 64x32, BK=32, 2-stage cp.async.
// Smem tiles: Ah|Al|Bh|Bl, 128 rows x 64B, 16B-chunk swizzle ch^((row>>1)&3).
// ---------------------------------------------------------------------------
#define TILE_B 8192
#define STAGE_B 32768
#define DSMEM_B (2 * STAGE_B)

#define LDSM_X4(R, ADDR) \
    asm volatile("ldmatrix.sync.aligned.m8n8.x4.shared.b16 {%0,%1,%2,%3}, [%4];" \
        : "=r"((R)[0]), "=r"((R)[1]), "=r"((R)[2]), "=r"((R)[3]) : "r"(ADDR))
#define LDSM_X2(R, ADDR) \
    asm volatile("ldmatrix.sync.aligned.m8n8.x2.shared.b16 {%0,%1}, [%2];" \
        : "=r"((R)[0]), "=r"((R)[1]) : "r"(ADDR))
#define MMA16816(C, A, B) \
    asm volatile("mma.sync.aligned.m16n8k16.row.col.f32.bf16.bf16.f32 " \
        "{%0,%1,%2,%3}, {%4,%5,%6,%7}, {%8,%9}, {%0,%1,%2,%3};" \
        : "+f"((C)[0]), "+f"((C)[1]), "+f"((C)[2]), "+f"((C)[3]) \
        : "r"((A)[0]), "r"((A)[1]), "r"((A)[2]), "r"((A)[3]), \
          "r"((B)[0]), "r"((B)[1]))
#define CP16(DST, SRC) \
    asm volatile("cp.async.cg.shared.global [%0], [%1], 16;" \
        :: "r"(DST), "l"(SRC) : "memory")

__global__ __launch_bounds__(256, 1) void hmma_gemm_kernel(
    const float* __restrict__ conv_b, float* __restrict__ out) {
    extern __shared__ __align__(128) char dsm[];
    __shared__ float s_bias[128];

    const int tid = threadIdx.x, lane = tid & 31, wid = tid >> 5;
    const int m0 = blockIdx.y * 128, n0 = blockIdx.x * 128;
    const int wm = wid >> 2, wn = wid & 3;
    const uint32_t sbase = smem_u32(dsm);
    if (tid < 128) s_bias[tid] = conv_b[n0 + tid];

    // ---- cp.async mapping: 8 x 16B chunks per thread per stage ----
    const __nv_bfloat16* gp[8];
    uint32_t doff[8];
#pragma unroll
    for (int i = 0; i < 8; ++i) {
        int cid = tid + i * 256;
        int tile = cid >> 9, row = (cid >> 2) & 127, ch = cid & 3;
        const __nv_bfloat16* base =
            (tile == 0) ? g_Ah + (size_t)(m0 + row) * KK :
            (tile == 1) ? g_Al + (size_t)(m0 + row) * KK :
            (tile == 2) ? g_Bh + (size_t)(n0 + row) * KK :
                          g_Bl + (size_t)(n0 + row) * KK;
        gp[i] = base + ch * 8;
        doff[i] = tile * TILE_B + row * 64 + ((ch ^ ((row >> 1) & 3)) * 16);
    }

    // ---- ldmatrix lane constants ----
    const int aq = lane >> 3;
    const int aml = wm * 64 + (aq & 1) * 8 + (lane & 7);
    const int acp = aq >> 1;
    const int as  = (aml >> 1) & 3;
    const int bql = (lane >> 3) & 1;
    const int bnl = wn * 32 + (lane & 7);
    const int bs  = (bnl >> 1) & 3;

    float acc[4][4][4];
#pragma unroll
    for (int mi = 0; mi < 4; ++mi)
#pragma unroll
        for (int ni = 0; ni < 4; ++ni)
#pragma unroll
            for (int r = 0; r < 4; ++r) acc[mi][ni][r] = 0.f;

    // ---- prologue: stage 0 ----
#pragma unroll
    for (int i = 0; i < 8; ++i) CP16(sbase + doff[i], gp[i]);
    asm volatile("cp.async.commit_group;" ::: "memory");

    for (int c = 0; c < NCH; ++c) {
        if (c + 1 < NCH) {
            uint32_t sb = sbase + ((c + 1) & 1) * STAGE_B;
            const __nv_bfloat16* off = (const __nv_bfloat16*)0 + (size_t)(c + 1) * 32;
#pragma unroll
            for (int i = 0; i < 8; ++i) CP16(sb + doff[i], gp[i] + (size_t)(c + 1) * 32);
            asm volatile("cp.async.commit_group;" ::: "memory");
            asm volatile("cp.async.wait_group 1;" ::: "memory");
            (void)off;
        } else {
            asm volatile("cp.async.wait_group 0;" ::: "memory");
        }
        __syncthreads();

        const uint32_t st = sbase + (c & 1) * STAGE_B;
#pragma unroll
        for (int kk = 0; kk < 2; ++kk) {
            uint32_t ah[4][4], al[4][4], bh[4][2], bl[4][2];
            const uint32_t aoff = aml * 64 + (((kk * 2 + acp) ^ as) * 16);
            const uint32_t boff = bnl * 64 + (((kk * 2 + bql) ^ bs) * 16);
#pragma unroll
            for (int mi = 0; mi < 4; ++mi) LDSM_X4(ah[mi], st + aoff + mi * 1024);
#pragma unroll
            for (int mi = 0; mi < 4; ++mi) LDSM_X4(al[mi], st + TILE_B + aoff + mi * 1024);
#pragma unroll
            for (int ni = 0; ni < 4; ++ni) LDSM_X2(bh[ni], st + 2 * TILE_B + boff + ni * 512);
#pragma unroll
            for (int ni = 0; ni < 4; ++ni) LDSM_X2(bl[ni], st + 3 * TILE_B + boff + ni * 512);
#pragma unroll
            for (int mi = 0; mi < 4; ++mi)
#pragma unroll
                for (int ni = 0; ni < 4; ++ni) MMA16816(acc[mi][ni], ah[mi], bh[ni]);
#pragma unroll
            for (int mi = 0; mi < 4; ++mi)
#pragma unroll
                for (int ni = 0; ni < 4; ++ni) MMA16816(acc[mi][ni], ah[mi], bl[ni]);
#pragma unroll
            for (int mi = 0; mi < 4; ++mi)
#pragma unroll
                for (int ni = 0; ni < 4; ++ni) MMA16816(acc[mi][ni], al[mi], bh[ni]);
        }
        __syncthreads();
    }

    // ---- epilogue: bias + relu, out[(m>>5)*32768 + o*32 + (m&31)] ----
    const int g = lane >> 2, t = lane & 3;
#pragma unroll
    for (int mi = 0; mi < 4; ++mi) {
#pragma unroll
        for (int ni = 0; ni < 4; ++ni) {
            int mA = m0 + wm * 64 + mi * 16 + g;
            int oL = wn * 32 + ni * 8 + 2 * t;
            int oA = n0 + oL;
            float b0 = s_bias[oL], b1 = s_bias[oL + 1];
            float v;
            v = acc[mi][ni][0] + b0;
            out[(size_t)(mA >> 5) * 32768 + (size_t)oA * 32 + (mA & 31)] = v > 0.f ? v : 0.f;
            v = acc[mi][ni][1] + b1;
            out[(size_t)(mA >> 5) * 32768 + (size_t)(oA + 1) * 32 + (mA & 31)] = v > 0.f ? v : 0.f;
            int mB = mA + 8;
            v = acc[mi][ni][2] + b0;
            out[(size_t)(mB >> 5) * 32768 + (size_t)oA * 32 + (mB & 31)] = v > 0.f ? v : 0.f;
            v = acc[mi][ni][3] + b1;
            out[(size_t)(mB >> 5) * 32768 + (size_t)(oA + 1) * 32 + (mB & 31)] = v > 0.f ? v : 0.f;
        }
    }
}

// ---------------------------------------------------------------------------
extern "C" void kernel_launch(void* const* d_in, const int* in_sizes, int n_in,
                              void* d_out, int out_size) {
    const float* f1     = (const float*)d_in[0];   // [1024, 1024]
    const float* conv_w = (const float*)d_in[1];   // [1024, 1024, 16, 1]
    const float* conv_b = (const float*)d_in[2];   // [1024]
    float* out = (float*)d_out;                    // [1024, 2048]

    cudaFuncSetAttribute(hmma_gemm_kernel,
                         cudaFuncAttributeMaxDynamicSharedMemorySize, DSMEM_B);

    topk_kernel<<<NN, 256>>>(f1);
    rows_kernel<<<(NPAIR * 64 + 255) / 256, 256>>>();
    build_A_kernel<<<dim3(NPAIR, 64), 256>>>(f1);
    build_B_kernel<<<NN, 256>>>(conv_w);
    hmma_gemm_kernel<<<dim3(8, 16), 256, DSMEM_B>>>(conv_b, out);
    (void)in_sizes; (void)n_in; (void)out_size;
}

// round 5
// speedup vs baseline: 2.8061x; 1.0852x over previous
#include <cuda_runtime.h>
#include <cuda_bf16.h>
#include <cstdint>

#define NN 1024
#define TOPK 16
#define NPAIR 272           // 256 pos (c_hi,t) pairs + 16 rep c_hi slices
#define KK (NPAIR * 32)     // 8704
#define MM 2048             // (b, w)
#define NCH64 (KK / 64)     // 136 K-chunks of 64

// Scratch (device globals: allocation-free per harness rules)
__device__ int            g_idx[NN * TOPK];
__device__ int            g_row[NPAIR * 64];
__device__ __nv_bfloat16  g_Ah[(size_t)MM * KK];
__device__ __nv_bfloat16  g_Al[(size_t)MM * KK];
__device__ __nv_bfloat16  g_Bh[(size_t)NN * KK];
__device__ __nv_bfloat16  g_Bl[(size_t)NN * KK];

__device__ __forceinline__ uint32_t smem_u32(const void* p) {
    uint32_t a;
    asm("{ .reg .u64 t; cvta.to.shared.u64 t, %1; cvt.u32.u64 %0, t; }"
        : "=r"(a) : "l"(p));
    return a;
}
__device__ __forceinline__ void split_bf16(float x, __nv_bfloat16& h, __nv_bfloat16& l) {
    h = __float2bfloat16(x);
    l = __float2bfloat16(x - __bfloat162float(h));
}

// ---------------------------------------------------------------------------
// Kernel 1: exact top-16 per row. 1024 threads, 1 element/thread in register,
// shfl-based (val, idx) reduction; ties -> lowest index.
// ---------------------------------------------------------------------------
__global__ __launch_bounds__(1024) void topk_kernel(const float* __restrict__ f1) {
    __shared__ float wv[32];
    __shared__ int   wi[32];
    __shared__ int   s_best;
    const int n = blockIdx.x, tid = threadIdx.x;
    const int lane = tid & 31, w = tid >> 5;
    float v = f1[n * NN + tid];
    const float NEG_INF = __int_as_float(0xff800000);

    for (int it = 0; it < TOPK; ++it) {
        float rv = v; int ri = tid;
#pragma unroll
        for (int s = 16; s > 0; s >>= 1) {
            float ov = __shfl_down_sync(0xffffffffu, rv, s);
            int   oi = __shfl_down_sync(0xffffffffu, ri, s);
            if (ov > rv || (ov == rv && oi < ri)) { rv = ov; ri = oi; }
        }
        if (lane == 0) { wv[w] = rv; wi[w] = ri; }
        __syncthreads();
        if (w == 0) {
            float rv2 = wv[lane]; int ri2 = wi[lane];
#pragma unroll
            for (int s = 16; s > 0; s >>= 1) {
                float ov = __shfl_down_sync(0xffffffffu, rv2, s);
                int   oi = __shfl_down_sync(0xffffffffu, ri2, s);
                if (ov > rv2 || (ov == rv2 && oi < ri2)) { rv2 = ov; ri2 = oi; }
            }
            if (lane == 0) { g_idx[n * TOPK + it] = ri2; s_best = ri2; }
        }
        __syncthreads();
        if (tid == s_best) v = NEG_INF;
    }
}

// ---------------------------------------------------------------------------
// Kernel 2: row-index table
// ---------------------------------------------------------------------------
__global__ void rows_kernel() {
    int i = blockIdx.x * blockDim.x + threadIdx.x;
    if (i >= NPAIR * 64) return;
    int pair = i >> 6, b = i & 63;
    int r;
    if (pair < 256) {
        int c_hi = pair >> 4, t = pair & 15;
        r = g_idx[(b * TOPK + c_hi) * TOPK + t];
    } else {
        r = b * TOPK + (pair - 256);
    }
    g_row[i] = r;
}

// ---------------------------------------------------------------------------
// Kernel 3a: build split-bf16 A [MM, KK] K-major.
//   A[b*32+w][pair*32 + c2*16 + h] = f1[g_row[pair,b], c2*512 + h*32 + w]
// ---------------------------------------------------------------------------
__global__ void build_A_kernel(const float* __restrict__ f1) {
    __shared__ float s[1024];
    const int pair = blockIdx.x, b = blockIdx.y, tid = threadIdx.x;
    const int r = g_row[pair * 64 + b];
    for (int i = tid; i < 1024; i += 256) s[i] = f1[r * NN + i];
    __syncthreads();
    const int w  = tid >> 3;
    const int j0 = (tid & 7) * 4;
    const size_t obase = (size_t)(b * 32 + w) * KK + pair * 32;
#pragma unroll
    for (int q = 0; q < 4; ++q) {
        int j = j0 + q;
        float v = s[(j >> 4) * 512 + (j & 15) * 32 + w];
        __nv_bfloat16 h, l; split_bf16(v, h, l);
        g_Ah[obase + j] = h;
        g_Al[obase + j] = l;
    }
}

// ---------------------------------------------------------------------------
// Kernel 3b: build split-bf16 B [NN, KK] K-major.
// ---------------------------------------------------------------------------
__global__ void build_B_kernel(const float* __restrict__ conv_w) {
    const int o = blockIdx.x;
    const float* cw = conv_w + (size_t)o * 16384;
    for (int k = threadIdx.x; k < KK; k += 256) {
        int pair = k >> 5, j = k & 31, c2 = j >> 4, h = j & 15;
        float v;
        if (pair < 256) {
            int ch = pair >> 4, t = pair & 15;
            v = cw[(ch * 64 + t * 4 + 2 + c2) * 16 + h];
        } else {
            int ch = pair - 256;
            v = 0.f;
#pragma unroll
            for (int t = 0; t < 16; ++t) v += cw[(ch * 64 + t * 4 + c2) * 16 + h];
        }
        __nv_bfloat16 hh, ll; split_bf16(v, hh, ll);
        g_Bh[(size_t)o * KK + k] = hh;
        g_Bl[(size_t)o * KK + k] = ll;
    }
}

// ---------------------------------------------------------------------------
// Kernel 4: HMMA GEMM (mma.sync bf16). C = AhBh + AhBl + AlBh, bias+relu.
// CTA tile 128x128, 8 warps (2x4), warp tile 64x32, BK=64, 2-stage cp.async.
// Smem: Ah|Al|Bh|Bl tiles of 128 rows x 128B; swizzle ch ^= (row & 7).
// ---------------------------------------------------------------------------
#define TILE_B 16384
#define STAGE_B 65536
#define DSMEM_B (2 * STAGE_B)

#define LDSM_X4(R, ADDR) \
    asm volatile("ldmatrix.sync.aligned.m8n8.x4.shared.b16 {%0,%1,%2,%3}, [%4];" \
        : "=r"((R)[0]), "=r"((R)[1]), "=r"((R)[2]), "=r"((R)[3]) : "r"(ADDR))
#define LDSM_X2(R, ADDR) \
    asm volatile("ldmatrix.sync.aligned.m8n8.x2.shared.b16 {%0,%1}, [%2];" \
        : "=r"((R)[0]), "=r"((R)[1]) : "r"(ADDR))
#define MMA16816(C, A, B) \
    asm volatile("mma.sync.aligned.m16n8k16.row.col.f32.bf16.bf16.f32 " \
        "{%0,%1,%2,%3}, {%4,%5,%6,%7}, {%8,%9}, {%0,%1,%2,%3};" \
        : "+f"((C)[0]), "+f"((C)[1]), "+f"((C)[2]), "+f"((C)[3]) \
        : "r"((A)[0]), "r"((A)[1]), "r"((A)[2]), "r"((A)[3]), \
          "r"((B)[0]), "r"((B)[1]))
#define CP16(DST, SRC) \
    asm volatile("cp.async.cg.shared.global [%0], [%1], 16;" \
        :: "r"(DST), "l"(SRC) : "memory")

__global__ __launch_bounds__(256, 1) void hmma_gemm_kernel(
    const float* __restrict__ conv_b, float* __restrict__ out) {
    extern __shared__ __align__(128) char dsm[];
    __shared__ float s_bias[128];

    const int tid = threadIdx.x, lane = tid & 31, wid = tid >> 5;
    const int m0 = blockIdx.y * 128, n0 = blockIdx.x * 128;
    const int wm = wid >> 2, wn = wid & 3;
    const uint32_t sbase = smem_u32(dsm);
    if (tid < 128) s_bias[tid] = conv_b[n0 + tid];

    // ---- cp.async mapping: 16 x 16B chunks per thread per stage ----
    const __nv_bfloat16* gp[16];
    uint32_t doff[16];
#pragma unroll
    for (int i = 0; i < 16; ++i) {
        int cid = tid + i * 256;
        int tile = cid >> 10, row = (cid >> 3) & 127, ch = cid & 7;
        const __nv_bfloat16* base =
            (tile == 0) ? g_Ah + (size_t)(m0 + row) * KK :
            (tile == 1) ? g_Al + (size_t)(m0 + row) * KK :
            (tile == 2) ? g_Bh + (size_t)(n0 + row) * KK :
                          g_Bl + (size_t)(n0 + row) * KK;
        gp[i] = base + ch * 8;
        doff[i] = tile * TILE_B + row * 128 + ((ch ^ (row & 7)) * 16);
    }

    // ---- ldmatrix lane constants ----
    const int aq  = lane >> 3;
    const int aml = wm * 64 + (aq & 1) * 8 + (lane & 7);   // A row (mi adds 16)
    const int acp = aq >> 1;
    const int as  = aml & 7;
    const int bql = (lane >> 3) & 1;
    const int bnl = wn * 32 + (lane & 7);                  // B row (ni adds 8)
    const int bs  = bnl & 7;

    float acc[4][4][4];
#pragma unroll
    for (int mi = 0; mi < 4; ++mi)
#pragma unroll
        for (int ni = 0; ni < 4; ++ni)
#pragma unroll
            for (int r = 0; r < 4; ++r) acc[mi][ni][r] = 0.f;

    // ---- prologue: stage 0 ----
#pragma unroll
    for (int i = 0; i < 16; ++i) CP16(sbase + doff[i], gp[i]);
    asm volatile("cp.async.commit_group;" ::: "memory");

    for (int c = 0; c < NCH64; ++c) {
        if (c + 1 < NCH64) {
            uint32_t sb = sbase + ((c + 1) & 1) * STAGE_B;
#pragma unroll
            for (int i = 0; i < 16; ++i) CP16(sb + doff[i], gp[i] + (size_t)(c + 1) * 64);
            asm volatile("cp.async.commit_group;" ::: "memory");
            asm volatile("cp.async.wait_group 1;" ::: "memory");
        } else {
            asm volatile("cp.async.wait_group 0;" ::: "memory");
        }
        __syncthreads();

        const uint32_t st = sbase + (c & 1) * STAGE_B;
#pragma unroll
        for (int kk = 0; kk < 4; ++kk) {
            uint32_t ah[4][4], al[4][4], bh[4][2], bl[4][2];
            const uint32_t aoff = aml * 128 + (((kk * 2 + acp) ^ as) * 16);
            const uint32_t boff = bnl * 128 + (((kk * 2 + bql) ^ bs) * 16);
#pragma unroll
            for (int mi = 0; mi < 4; ++mi) LDSM_X4(ah[mi], st + aoff + mi * 2048);
#pragma unroll
            for (int mi = 0; mi < 4; ++mi) LDSM_X4(al[mi], st + TILE_B + aoff + mi * 2048);
#pragma unroll
            for (int ni = 0; ni < 4; ++ni) LDSM_X2(bh[ni], st + 2 * TILE_B + boff + ni * 1024);
#pragma unroll
            for (int ni = 0; ni < 4; ++ni) LDSM_X2(bl[ni], st + 3 * TILE_B + boff + ni * 1024);
#pragma unroll
            for (int mi = 0; mi < 4; ++mi)
#pragma unroll
                for (int ni = 0; ni < 4; ++ni) MMA16816(acc[mi][ni], ah[mi], bh[ni]);
#pragma unroll
            for (int mi = 0; mi < 4; ++mi)
#pragma unroll
                for (int ni = 0; ni < 4; ++ni) MMA16816(acc[mi][ni], ah[mi], bl[ni]);
#pragma unroll
            for (int mi = 0; mi < 4; ++mi)
#pragma unroll
                for (int ni = 0; ni < 4; ++ni) MMA16816(acc[mi][ni], al[mi], bh[ni]);
        }
        __syncthreads();
    }

    // ---- epilogue: bias + relu, out[(m>>5)*32768 + o*32 + (m&31)] ----
    const int g = lane >> 2, t = lane & 3;
#pragma unroll
    for (int mi = 0; mi < 4; ++mi) {
#pragma unroll
        for (int ni = 0; ni < 4; ++ni) {
            int mA = m0 + wm * 64 + mi * 16 + g;
            int oL = wn * 32 + ni * 8 + 2 * t;
            int oA = n0 + oL;
            float b0 = s_bias[oL], b1 = s_bias[oL + 1];
            float v;
            v = acc[mi][ni][0] + b0;
            out[(size_t)(mA >> 5) * 32768 + (size_t)oA * 32 + (mA & 31)] = v > 0.f ? v : 0.f;
            v = acc[mi][ni][1] + b1;
            out[(size_t)(mA >> 5) * 32768 + (size_t)(oA + 1) * 32 + (mA & 31)] = v > 0.f ? v : 0.f;
            int mB = mA + 8;
            v = acc[mi][ni][2] + b0;
            out[(size_t)(mB >> 5) * 32768 + (size_t)oA * 32 + (mB & 31)] = v > 0.f ? v : 0.f;
            v = acc[mi][ni][3] + b1;
            out[(size_t)(mB >> 5) * 32768 + (size_t)(oA + 1) * 32 + (mB & 31)] = v > 0.f ? v : 0.f;
        }
    }
}

// ---------------------------------------------------------------------------
extern "C" void kernel_launch(void* const* d_in, const int* in_sizes, int n_in,
                              void* d_out, int out_size) {
    const float* f1     = (const float*)d_in[0];   // [1024, 1024]
    const float* conv_w = (const float*)d_in[1];   // [1024, 1024, 16, 1]
    const float* conv_b = (const float*)d_in[2];   // [1024]
    float* out = (float*)d_out;                    // [1024, 2048]

    cudaFuncSetAttribute(hmma_gemm_kernel,
                         cudaFuncAttributeMaxDynamicSharedMemorySize, DSMEM_B);

    topk_kernel<<<NN, 1024>>>(f1);
    rows_kernel<<<(NPAIR * 64 + 255) / 256, 256>>>();
    build_A_kernel<<<dim3(NPAIR, 64), 256>>>(f1);
    build_B_kernel<<<NN, 256>>>(conv_w);
    hmma_gemm_kernel<<<dim3(8, 16), 256, DSMEM_B>>>(conv_b, out);
    (void)in_sizes; (void)n_in; (void)out_size;
}

// round 6
// speedup vs baseline: 2.8169x; 1.0039x over previous
#include <cuda_runtime.h>
#include <cuda_bf16.h>
#include <cstdint>

#define NN 1024
#define TOPK 16
#define NPAIR 272           // 256 pos (c_hi,t) pairs + 16 rep c_hi slices
#define KK (NPAIR * 32)     // 8704
#define MM 2048             // (b, w)
#define NCH64 (KK / 64)     // 136 K-chunks of 64

// Scratch (device globals: allocation-free per harness rules)
__device__ int            g_row[NPAIR * 64];
__device__ __nv_bfloat16  g_Ah[(size_t)MM * KK];
__device__ __nv_bfloat16  g_Al[(size_t)MM * KK];
__device__ __nv_bfloat16  g_Bh[(size_t)NN * KK];
__device__ __nv_bfloat16  g_Bl[(size_t)NN * KK];

__device__ __forceinline__ uint32_t smem_u32(const void* p) {
    uint32_t a;
    asm("{ .reg .u64 t; cvta.to.shared.u64 t, %1; cvt.u32.u64 %0, t; }"
        : "=r"(a) : "l"(p));
    return a;
}
__device__ __forceinline__ void split_bf16(float x, __nv_bfloat16& h, __nv_bfloat16& l) {
    h = __float2bfloat16(x);
    l = __float2bfloat16(x - __bfloat162float(h));
}

// ---------------------------------------------------------------------------
// Kernel 1: exact top-16 per row (ties -> lowest index), plus direct g_row
// emission (rows for n = b*16+c_hi are block-local).
// ---------------------------------------------------------------------------
__global__ __launch_bounds__(1024) void topk_kernel(const float* __restrict__ f1) {
    __shared__ float wv[32];
    __shared__ int   wi[32];
    __shared__ int   s_best;
    __shared__ int   s_idx[TOPK];
    const int n = blockIdx.x, tid = threadIdx.x;
    const int lane = tid & 31, w = tid >> 5;
    float v = f1[n * NN + tid];
    const float NEG_INF = __int_as_float(0xff800000);

    for (int it = 0; it < TOPK; ++it) {
        float rv = v; int ri = tid;
#pragma unroll
        for (int s = 16; s > 0; s >>= 1) {
            float ov = __shfl_down_sync(0xffffffffu, rv, s);
            int   oi = __shfl_down_sync(0xffffffffu, ri, s);
            if (ov > rv || (ov == rv && oi < ri)) { rv = ov; ri = oi; }
        }
        if (lane == 0) { wv[w] = rv; wi[w] = ri; }
        __syncthreads();
        if (w == 0) {
            float rv2 = wv[lane]; int ri2 = wi[lane];
#pragma unroll
            for (int s = 16; s > 0; s >>= 1) {
                float ov = __shfl_down_sync(0xffffffffu, rv2, s);
                int   oi = __shfl_down_sync(0xffffffffu, ri2, s);
                if (ov > rv2 || (ov == rv2 && oi < ri2)) { rv2 = ov; ri2 = oi; }
            }
            if (lane == 0) { s_idx[it] = ri2; s_best = ri2; }
        }
        __syncthreads();
        if (tid == s_best) v = NEG_INF;
    }
    // emit g_row: n = b*16 + c_hi. pos: pair = c_hi*16 + t. rep: pair = 256 + c_hi.
    const int b = n >> 4, c_hi = n & 15;
    if (tid < TOPK) g_row[(c_hi * 16 + tid) * 64 + b] = s_idx[tid];
    if (tid == TOPK) g_row[(256 + c_hi) * 64 + b] = n;
}

// ---------------------------------------------------------------------------
// Kernel 2: build split-bf16 A [MM, KK] K-major.
//   A[b*32+w][pair*32 + c2*16 + h] = f1[g_row[pair,b], c2*512 + h*32 + w]
// ---------------------------------------------------------------------------
__global__ void build_A_kernel(const float* __restrict__ f1) {
    __shared__ float s[1024];
    const int pair = blockIdx.x, b = blockIdx.y, tid = threadIdx.x;
    const int r = g_row[pair * 64 + b];
    for (int i = tid; i < 1024; i += 256) s[i] = f1[r * NN + i];
    __syncthreads();
    const int w  = tid >> 3;
    const int j0 = (tid & 7) * 4;
    const size_t obase = (size_t)(b * 32 + w) * KK + pair * 32;
#pragma unroll
    for (int q = 0; q < 4; ++q) {
        int j = j0 + q;
        float v = s[(j >> 4) * 512 + (j & 15) * 32 + w];
        __nv_bfloat16 h, l; split_bf16(v, h, l);
        g_Ah[obase + j] = h;
        g_Al[obase + j] = l;
    }
}

// ---------------------------------------------------------------------------
// Kernel 3: build split-bf16 B [NN, KK] K-major.
// ---------------------------------------------------------------------------
__global__ void build_B_kernel(const float* __restrict__ conv_w) {
    const int o = blockIdx.x;
    const float* cw = conv_w + (size_t)o * 16384;
    for (int k = threadIdx.x; k < KK; k += 256) {
        int pair = k >> 5, j = k & 31, c2 = j >> 4, h = j & 15;
        float v;
        if (pair < 256) {
            int ch = pair >> 4, t = pair & 15;
            v = cw[(ch * 64 + t * 4 + 2 + c2) * 16 + h];
        } else {
            int ch = pair - 256;
            v = 0.f;
#pragma unroll
            for (int t = 0; t < 16; ++t) v += cw[(ch * 64 + t * 4 + c2) * 16 + h];
        }
        __nv_bfloat16 hh, ll; split_bf16(v, hh, ll);
        g_Bh[(size_t)o * KK + k] = hh;
        g_Bl[(size_t)o * KK + k] = ll;
    }
}

// ---------------------------------------------------------------------------
// Kernel 4: HMMA GEMM. C = AhBh + AhBl + AlBh, bias+relu.
// CTA tile 128x128, 8 warps (2x4), warp tile 64x32, BK=64.
// 3-stage cp.async pipeline, single __syncthreads per chunk.
// Smem: Ah|Al|Bh|Bl tiles of 128 rows x 128B; swizzle ch ^= (row & 7).
// ---------------------------------------------------------------------------
#define TILE_B 16384
#define STAGE_B 65536
#define DSMEM_B (3 * STAGE_B)

#define LDSM_X4(R, ADDR) \
    asm volatile("ldmatrix.sync.aligned.m8n8.x4.shared.b16 {%0,%1,%2,%3}, [%4];" \
        : "=r"((R)[0]), "=r"((R)[1]), "=r"((R)[2]), "=r"((R)[3]) : "r"(ADDR))
#define LDSM_X2(R, ADDR) \
    asm volatile("ldmatrix.sync.aligned.m8n8.x2.shared.b16 {%0,%1}, [%2];" \
        : "=r"((R)[0]), "=r"((R)[1]) : "r"(ADDR))
#define MMA16816(C, A, B) \
    asm volatile("mma.sync.aligned.m16n8k16.row.col.f32.bf16.bf16.f32 " \
        "{%0,%1,%2,%3}, {%4,%5,%6,%7}, {%8,%9}, {%0,%1,%2,%3};" \
        : "+f"((C)[0]), "+f"((C)[1]), "+f"((C)[2]), "+f"((C)[3]) \
        : "r"((A)[0]), "r"((A)[1]), "r"((A)[2]), "r"((A)[3]), \
          "r"((B)[0]), "r"((B)[1]))
#define CP16(DST, SRC) \
    asm volatile("cp.async.cg.shared.global [%0], [%1], 16;" \
        :: "r"(DST), "l"(SRC) : "memory")

__global__ __launch_bounds__(256, 1) void hmma_gemm_kernel(
    const float* __restrict__ conv_b, float* __restrict__ out) {
    extern __shared__ __align__(128) char dsm[];
    __shared__ float s_bias[128];

    const int tid = threadIdx.x, lane = tid & 31, wid = tid >> 5;
    const int m0 = blockIdx.y * 128, n0 = blockIdx.x * 128;
    const int wm = wid >> 2, wn = wid & 3;
    const uint32_t sbase = smem_u32(dsm);
    if (tid < 128) s_bias[tid] = conv_b[n0 + tid];

    // ---- cp.async mapping: 16 x 16B chunks per thread per stage ----
    const __nv_bfloat16* gp[16];
    uint32_t doff[16];
#pragma unroll
    for (int i = 0; i < 16; ++i) {
        int cid = tid + i * 256;
        int tile = cid >> 10, row = (cid >> 3) & 127, ch = cid & 7;
        const __nv_bfloat16* base =
            (tile == 0) ? g_Ah + (size_t)(m0 + row) * KK :
            (tile == 1) ? g_Al + (size_t)(m0 + row) * KK :
            (tile == 2) ? g_Bh + (size_t)(n0 + row) * KK :
                          g_Bl + (size_t)(n0 + row) * KK;
        gp[i] = base + ch * 8;
        doff[i] = tile * TILE_B + row * 128 + ((ch ^ (row & 7)) * 16);
    }

    // ---- ldmatrix lane constants ----
    const int aq  = lane >> 3;
    const int aml = wm * 64 + (aq & 1) * 8 + (lane & 7);   // A row (mi adds 16)
    const int acp = aq >> 1;
    const int as  = aml & 7;
    const int bql = (lane >> 3) & 1;
    const int bnl = wn * 32 + (lane & 7);                  // B row (ni adds 8)
    const int bs  = bnl & 7;

    float acc[4][4][4];
#pragma unroll
    for (int mi = 0; mi < 4; ++mi)
#pragma unroll
        for (int ni = 0; ni < 4; ++ni)
#pragma unroll
            for (int r = 0; r < 4; ++r) acc[mi][ni][r] = 0.f;

    // ---- prologue: stages 0 and 1 ----
#pragma unroll
    for (int i = 0; i < 16; ++i) CP16(sbase + doff[i], gp[i]);
    asm volatile("cp.async.commit_group;" ::: "memory");
#pragma unroll
    for (int i = 0; i < 16; ++i) CP16(sbase + STAGE_B + doff[i], gp[i] + 64);
    asm volatile("cp.async.commit_group;" ::: "memory");

    int slot = 0, nslot = 2;
    for (int c = 0; c < NCH64; ++c) {
        if (c + 1 < NCH64) {
            asm volatile("cp.async.wait_group 1;" ::: "memory");
        } else {
            asm volatile("cp.async.wait_group 0;" ::: "memory");
        }
        __syncthreads();   // stage c visible to all; slot nslot free (consumed at c-1)

        if (c + 2 < NCH64) {
            uint32_t sb = sbase + nslot * STAGE_B;
            const size_t ko = (size_t)(c + 2) * 64;
#pragma unroll
            for (int i = 0; i < 16; ++i) CP16(sb + doff[i], gp[i] + ko);
            asm volatile("cp.async.commit_group;" ::: "memory");
        }

        const uint32_t st = sbase + slot * STAGE_B;
#pragma unroll
        for (int kk = 0; kk < 4; ++kk) {
            uint32_t ah[4][4], al[4][4], bh[4][2], bl[4][2];
            const uint32_t aoff = aml * 128 + (((kk * 2 + acp) ^ as) * 16);
            const uint32_t boff = bnl * 128 + (((kk * 2 + bql) ^ bs) * 16);
#pragma unroll
            for (int mi = 0; mi < 4; ++mi) LDSM_X4(ah[mi], st + aoff + mi * 2048);
#pragma unroll
            for (int mi = 0; mi < 4; ++mi) LDSM_X4(al[mi], st + TILE_B + aoff + mi * 2048);
#pragma unroll
            for (int ni = 0; ni < 4; ++ni) LDSM_X2(bh[ni], st + 2 * TILE_B + boff + ni * 1024);
#pragma unroll
            for (int ni = 0; ni < 4; ++ni) LDSM_X2(bl[ni], st + 3 * TILE_B + boff + ni * 1024);
#pragma unroll
            for (int mi = 0; mi < 4; ++mi)
#pragma unroll
                for (int ni = 0; ni < 4; ++ni) MMA16816(acc[mi][ni], ah[mi], bh[ni]);
#pragma unroll
            for (int mi = 0; mi < 4; ++mi)
#pragma unroll
                for (int ni = 0; ni < 4; ++ni) MMA16816(acc[mi][ni], ah[mi], bl[ni]);
#pragma unroll
            for (int mi = 0; mi < 4; ++mi)
#pragma unroll
                for (int ni = 0; ni < 4; ++ni) MMA16816(acc[mi][ni], al[mi], bh[ni]);
        }
        slot = (slot + 1) % 3;
        nslot = (nslot + 1) % 3;
    }

    // ---- epilogue: bias + relu, out[(m>>5)*32768 + o*32 + (m&31)] ----
    const int g = lane >> 2, t = lane & 3;
#pragma unroll
    for (int mi = 0; mi < 4; ++mi) {
#pragma unroll
        for (int ni = 0; ni < 4; ++ni) {
            int mA = m0 + wm * 64 + mi * 16 + g;
            int oL = wn * 32 + ni * 8 + 2 * t;
            int oA = n0 + oL;
            float b0 = s_bias[oL], b1 = s_bias[oL + 1];
            float v;
            v = acc[mi][ni][0] + b0;
            out[(size_t)(mA >> 5) * 32768 + (size_t)oA * 32 + (mA & 31)] = v > 0.f ? v : 0.f;
            v = acc[mi][ni][1] + b1;
            out[(size_t)(mA >> 5) * 32768 + (size_t)(oA + 1) * 32 + (mA & 31)] = v > 0.f ? v : 0.f;
            int mB = mA + 8;
            v = acc[mi][ni][2] + b0;
            out[(size_t)(mB >> 5) * 32768 + (size_t)oA * 32 + (mB & 31)] = v > 0.f ? v : 0.f;
            v = acc[mi][ni][3] + b1;
            out[(size_t)(mB >> 5) * 32768 + (size_t)(oA + 1) * 32 + (mB & 31)] = v > 0.f ? v : 0.f;
        }
    }
}

// ---------------------------------------------------------------------------
extern "C" void kernel_launch(void* const* d_in, const int* in_sizes, int n_in,
                              void* d_out, int out_size) {
    const float* f1     = (const float*)d_in[0];   // [1024, 1024]
    const float* conv_w = (const float*)d_in[1];   // [1024, 1024, 16, 1]
    const float* conv_b = (const float*)d_in[2];   // [1024]
    float* out = (float*)d_out;                    // [1024, 2048]

    cudaFuncSetAttribute(hmma_gemm_kernel,
                         cudaFuncAttributeMaxDynamicSharedMemorySize, DSMEM_B);

    topk_kernel<<<NN, 1024>>>(f1);
    build_A_kernel<<<dim3(NPAIR, 64), 256>>>(f1);
    build_B_kernel<<<NN, 256>>>(conv_w);
    hmma_gemm_kernel<<<dim3(8, 16), 256, DSMEM_B>>>(conv_b, out);
    (void)in_sizes; (void)n_in; (void)out_size;
}

// round 8
// speedup vs baseline: 3.1725x; 1.1262x over previous
#include <cuda_runtime.h>
#include <cuda_bf16.h>
#include <cstdint>

#define NN 1024
#define TOPK 16
#define NPAIR 272           // 256 pos (c_hi,t) pairs + 16 rep c_hi slices
#define KK (NPAIR * 32)     // 8704
#define MM 2048             // (b, w)
#define NCH64 (KK / 64)     // 136 K-chunks of 64

// Scratch (device globals: allocation-free per harness rules)
__device__ int            g_row[NPAIR * 64];
__device__ __nv_bfloat16  g_Ah[(size_t)MM * KK];
__device__ __nv_bfloat16  g_Al[(size_t)MM * KK];
__device__ __nv_bfloat16  g_Bh[(size_t)NN * KK];
__device__ __nv_bfloat16  g_Bl[(size_t)NN * KK];

__device__ __forceinline__ uint32_t smem_u32(const void* p) {
    uint32_t a;
    asm("{ .reg .u64 t; cvta.to.shared.u64 t, %1; cvt.u32.u64 %0, t; }"
        : "=r"(a) : "l"(p));
    return a;
}
__device__ __forceinline__ void split_bf16(float x, __nv_bfloat16& h, __nv_bfloat16& l) {
    h = __float2bfloat16(x);
    l = __float2bfloat16(x - __bfloat162float(h));
}
__device__ __forceinline__ uint32_t pack_bf2(__nv_bfloat16 a, __nv_bfloat16 b) {
    __nv_bfloat162 v(a, b);
    return *(uint32_t*)&v;
}

// ---------------------------------------------------------------------------
// Kernel 1: exact top-16 per row (ties -> lowest index) + g_row emission.
// ---------------------------------------------------------------------------
__global__ __launch_bounds__(1024) void topk_kernel(const float* __restrict__ f1) {
    __shared__ float wv[32];
    __shared__ int   wi[32];
    __shared__ int   s_best;
    __shared__ int   s_idx[TOPK];
    const int n = blockIdx.x, tid = threadIdx.x;
    const int lane = tid & 31, w = tid >> 5;
    float v = f1[n * NN + tid];
    const float NEG_INF = __int_as_float(0xff800000);

    for (int it = 0; it < TOPK; ++it) {
        float rv = v; int ri = tid;
#pragma unroll
        for (int s = 16; s > 0; s >>= 1) {
            float ov = __shfl_down_sync(0xffffffffu, rv, s);
            int   oi = __shfl_down_sync(0xffffffffu, ri, s);
            if (ov > rv || (ov == rv && oi < ri)) { rv = ov; ri = oi; }
        }
        if (lane == 0) { wv[w] = rv; wi[w] = ri; }
        __syncthreads();
        if (w == 0) {
            float rv2 = wv[lane]; int ri2 = wi[lane];
#pragma unroll
            for (int s = 16; s > 0; s >>= 1) {
                float ov = __shfl_down_sync(0xffffffffu, rv2, s);
                int   oi = __shfl_down_sync(0xffffffffu, ri2, s);
                if (ov > rv2 || (ov == rv2 && oi < ri2)) { rv2 = ov; ri2 = oi; }
            }
            if (lane == 0) { s_idx[it] = ri2; s_best = ri2; }
        }
        __syncthreads();
        if (tid == s_best) v = NEG_INF;
    }
    const int b = n >> 4, c_hi = n & 15;
    if (tid < TOPK) g_row[(c_hi * 16 + tid) * 64 + b] = s_idx[tid];
    if (tid == TOPK) g_row[(256 + c_hi) * 64 + b] = n;
}

// ---------------------------------------------------------------------------
// Kernel 2: build split-bf16 A [MM, KK] K-major, packed 8B stores.
// ---------------------------------------------------------------------------
__global__ void build_A_kernel(const float* __restrict__ f1) {
    __shared__ float s[1024];
    const int pair = blockIdx.x, b = blockIdx.y, tid = threadIdx.x;
    const int r = g_row[pair * 64 + b];
    for (int i = tid; i < 1024; i += 256) s[i] = f1[r * NN + i];
    __syncthreads();
    const int w  = tid >> 3;
    const int j0 = (tid & 7) * 4;
    const size_t obase = (size_t)(b * 32 + w) * KK + pair * 32 + j0;
    __nv_bfloat16 h[4], l[4];
#pragma unroll
    for (int q = 0; q < 4; ++q) {
        int j = j0 + q;
        float v = s[(j >> 4) * 512 + (j & 15) * 32 + w];
        split_bf16(v, h[q], l[q]);
    }
    uint2 ph = make_uint2(pack_bf2(h[0], h[1]), pack_bf2(h[2], h[3]));
    uint2 pl = make_uint2(pack_bf2(l[0], l[1]), pack_bf2(l[2], l[3]));
    *(uint2*)&g_Ah[obase] = ph;
    *(uint2*)&g_Al[obase] = pl;
}

// ---------------------------------------------------------------------------
// Kernel 3: build split-bf16 B [NN, KK] K-major, float4 reads + 8B stores.
// ---------------------------------------------------------------------------
__global__ void build_B_kernel(const float* __restrict__ conv_w) {
    const int o = blockIdx.x;
    const float* cw = conv_w + (size_t)o * 16384;
    for (int k0 = threadIdx.x * 4; k0 < KK; k0 += 1024) {
        int pair = k0 >> 5, j = k0 & 31, c2 = j >> 4, h = j & 15;
        float4 v;
        if (pair < 256) {
            int ch = pair >> 4, t = pair & 15;
            v = *(const float4*)(cw + (ch * 64 + t * 4 + 2 + c2) * 16 + h);
        } else {
            int ch = pair - 256;
            v = make_float4(0.f, 0.f, 0.f, 0.f);
#pragma unroll
            for (int t = 0; t < 16; ++t) {
                float4 u = *(const float4*)(cw + (ch * 64 + t * 4 + c2) * 16 + h);
                v.x += u.x; v.y += u.y; v.z += u.z; v.w += u.w;
            }
        }
        __nv_bfloat16 hh[4], ll[4];
        split_bf16(v.x, hh[0], ll[0]); split_bf16(v.y, hh[1], ll[1]);
        split_bf16(v.z, hh[2], ll[2]); split_bf16(v.w, hh[3], ll[3]);
        uint2 ph = make_uint2(pack_bf2(hh[0], hh[1]), pack_bf2(hh[2], hh[3]));
        uint2 pl = make_uint2(pack_bf2(ll[0], ll[1]), pack_bf2(ll[2], ll[3]));
        *(uint2*)&g_Bh[(size_t)o * KK + k0] = ph;
        *(uint2*)&g_Bl[(size_t)o * KK + k0] = pl;
    }
}

// ---------------------------------------------------------------------------
// Kernel 4: HMMA GEMM. C = AhBh + AhBl + AlBh, bias+relu.
// CTA 128x128, 8 warps (2x4), warp tile 64x32, BK=64, 3-stage cp.async,
// fragment double-buffering across kk, x4 ldmatrix for A and B.
// ---------------------------------------------------------------------------
#define TILE_B 16384
#define STAGE_B 65536
#define DSMEM_B (3 * STAGE_B)

#define LDSM_X4(R, ADDR) \
    asm volatile("ldmatrix.sync.aligned.m8n8.x4.shared.b16 {%0,%1,%2,%3}, [%4];" \
        : "=r"((R)[0]), "=r"((R)[1]), "=r"((R)[2]), "=r"((R)[3]) : "r"(ADDR))
#define MMA16816(C, A, B) \
    asm volatile("mma.sync.aligned.m16n8k16.row.col.f32.bf16.bf16.f32 " \
        "{%0,%1,%2,%3}, {%4,%5,%6,%7}, {%8,%9}, {%0,%1,%2,%3};" \
        : "+f"((C)[0]), "+f"((C)[1]), "+f"((C)[2]), "+f"((C)[3]) \
        : "r"((A)[0]), "r"((A)[1]), "r"((A)[2]), "r"((A)[3]), \
          "r"((B)[0]), "r"((B)[1]))
#define CP16(DST, SRC) \
    asm volatile("cp.async.cg.shared.global [%0], [%1], 16;" \
        :: "r"(DST), "l"(SRC) : "memory")

__global__ __launch_bounds__(256, 1) void hmma_gemm_kernel(
    const float* __restrict__ conv_b, float* __restrict__ out) {
    extern __shared__ __align__(128) char dsm[];
    __shared__ float s_bias[128];

    const int tid = threadIdx.x, lane = tid & 31, wid = tid >> 5;
    const int m0 = blockIdx.y * 128, n0 = blockIdx.x * 128;
    const int wm = wid >> 2, wn = wid & 3;
    const uint32_t sbase = smem_u32(dsm);
    if (tid < 128) s_bias[tid] = conv_b[n0 + tid];

    // ---- cp.async mapping: 16 x 16B chunks per thread per stage ----
    const __nv_bfloat16* gp[16];
    uint32_t doff[16];
#pragma unroll
    for (int i = 0; i < 16; ++i) {
        int cid = tid + i * 256;
        int tile = cid >> 10, row = (cid >> 3) & 127, ch = cid & 7;
        const __nv_bfloat16* base =
            (tile == 0) ? g_Ah + (size_t)(m0 + row) * KK :
            (tile == 1) ? g_Al + (size_t)(m0 + row) * KK :
            (tile == 2) ? g_Bh + (size_t)(n0 + row) * KK :
                          g_Bl + (size_t)(n0 + row) * KK;
        gp[i] = base + ch * 8;
        doff[i] = tile * TILE_B + row * 128 + ((ch ^ (row & 7)) * 16);
    }

    // ---- ldmatrix lane constants ----
    const int aq  = lane >> 3;
    const int aml = wm * 64 + (aq & 1) * 8 + (lane & 7);   // A row (mi adds 16)
    const int acp = aq >> 1;
    const int as  = aml & 7;
    // B x4: lanes 0-7: (q0, n0-7), 8-15: (q1, n0-7), 16-23: (q0, n8-15), 24-31: (q1, n8-15)
    const int bnl4 = wn * 32 + ((lane >> 4) & 1) * 8 + (lane & 7);  // (nj adds 16)
    const int bq4  = (lane >> 3) & 1;
    const int bs4  = bnl4 & 7;

    float acc[4][4][4];
#pragma unroll
    for (int mi = 0; mi < 4; ++mi)
#pragma unroll
        for (int ni = 0; ni < 4; ++ni)
#pragma unroll
            for (int r = 0; r < 4; ++r) acc[mi][ni][r] = 0.f;

    uint32_t ah[2][4][4], al[2][4][4], bh[2][2][4], bl[2][2][4];

    // ---- prologue: stages 0 and 1 ----
#pragma unroll
    for (int i = 0; i < 16; ++i) CP16(sbase + doff[i], gp[i]);
    asm volatile("cp.async.commit_group;" ::: "memory");
#pragma unroll
    for (int i = 0; i < 16; ++i) CP16(sbase + STAGE_B + doff[i], gp[i] + 64);
    asm volatile("cp.async.commit_group;" ::: "memory");

    int slot = 0, nslot = 2;
    for (int c = 0; c < NCH64; ++c) {
        if (c + 1 < NCH64) {
            asm volatile("cp.async.wait_group 1;" ::: "memory");
        } else {
            asm volatile("cp.async.wait_group 0;" ::: "memory");
        }
        __syncthreads();

        if (c + 2 < NCH64) {
            uint32_t sb = sbase + nslot * STAGE_B;
            const size_t ko = (size_t)(c + 2) * 64;
#pragma unroll
            for (int i = 0; i < 16; ++i) CP16(sb + doff[i], gp[i] + ko);
            asm volatile("cp.async.commit_group;" ::: "memory");
        }

        const uint32_t st = sbase + slot * STAGE_B;

        // load kk=0 fragments into buffer 0
        {
            const uint32_t aoff = aml * 128 + ((acp ^ as) * 16);
            const uint32_t boff = bnl4 * 128 + ((bq4 ^ bs4) * 16);
#pragma unroll
            for (int mi = 0; mi < 4; ++mi) LDSM_X4(ah[0][mi], st + aoff + mi * 2048);
#pragma unroll
            for (int mi = 0; mi < 4; ++mi) LDSM_X4(al[0][mi], st + TILE_B + aoff + mi * 2048);
#pragma unroll
            for (int nj = 0; nj < 2; ++nj) LDSM_X4(bh[0][nj], st + 2 * TILE_B + boff + nj * 2048);
#pragma unroll
            for (int nj = 0; nj < 2; ++nj) LDSM_X4(bl[0][nj], st + 3 * TILE_B + boff + nj * 2048);
        }

#pragma unroll
        for (int kk = 0; kk < 4; ++kk) {
            const int cb = kk & 1, nb = cb ^ 1;
            if (kk < 3) {   // prefetch kk+1 fragments
                const uint32_t aoff = aml * 128 + ((((kk + 1) * 2 + acp) ^ as) * 16);
                const uint32_t boff = bnl4 * 128 + ((((kk + 1) * 2 + bq4) ^ bs4) * 16);
#pragma unroll
                for (int mi = 0; mi < 4; ++mi) LDSM_X4(ah[nb][mi], st + aoff + mi * 2048);
#pragma unroll
                for (int mi = 0; mi < 4; ++mi) LDSM_X4(al[nb][mi], st + TILE_B + aoff + mi * 2048);
#pragma unroll
                for (int nj = 0; nj < 2; ++nj) LDSM_X4(bh[nb][nj], st + 2 * TILE_B + boff + nj * 2048);
#pragma unroll
                for (int nj = 0; nj < 2; ++nj) LDSM_X4(bl[nb][nj], st + 3 * TILE_B + boff + nj * 2048);
            }
#pragma unroll
            for (int mi = 0; mi < 4; ++mi)
#pragma unroll
                for (int nj = 0; nj < 2; ++nj) {
                    MMA16816(acc[mi][2 * nj],     ah[cb][mi], &bh[cb][nj][0]);
                    MMA16816(acc[mi][2 * nj + 1], ah[cb][mi], &bh[cb][nj][2]);
                }
#pragma unroll
            for (int mi = 0; mi < 4; ++mi)
#pragma unroll
                for (int nj = 0; nj < 2; ++nj) {
                    MMA16816(acc[mi][2 * nj],     ah[cb][mi], &bl[cb][nj][0]);
                    MMA16816(acc[mi][2 * nj + 1], ah[cb][mi], &bl[cb][nj][2]);
                }
#pragma unroll
            for (int mi = 0; mi < 4; ++mi)
#pragma unroll
                for (int nj = 0; nj < 2; ++nj) {
                    MMA16816(acc[mi][2 * nj],     al[cb][mi], &bh[cb][nj][0]);
                    MMA16816(acc[mi][2 * nj + 1], al[cb][mi], &bh[cb][nj][2]);
                }
        }
        slot = (slot + 1) % 3;
        nslot = (nslot + 1) % 3;
    }

    // ---- epilogue: bias + relu, out[(m>>5)*32768 + o*32 + (m&31)] ----
    const int g = lane >> 2, t = lane & 3;
#pragma unroll
    for (int mi = 0; mi < 4; ++mi) {
#pragma unroll
        for (int ni = 0; ni < 4; ++ni) {
            int mA = m0 + wm * 64 + mi * 16 + g;
            int oL = wn * 32 + ni * 8 + 2 * t;
            int oA = n0 + oL;
            float b0 = s_bias[oL], b1 = s_bias[oL + 1];
            float v;
            v = acc[mi][ni][0] + b0;
            out[(size_t)(mA >> 5) * 32768 + (size_t)oA * 32 + (mA & 31)] = v > 0.f ? v : 0.f;
            v = acc[mi][ni][1] + b1;
            out[(size_t)(mA >> 5) * 32768 + (size_t)(oA + 1) * 32 + (mA & 31)] = v > 0.f ? v : 0.f;
            int mB = mA + 8;
            v = acc[mi][ni][2] + b0;
            out[(size_t)(mB >> 5) * 32768 + (size_t)oA * 32 + (mB & 31)] = v > 0.f ? v : 0.f;
            v = acc[mi][ni][3] + b1;
            out[(size_t)(mB >> 5) * 32768 + (size_t)(oA + 1) * 32 + (mB & 31)] = v > 0.f ? v : 0.f;
        }
    }
}

// ---------------------------------------------------------------------------
extern "C" void kernel_launch(void* const* d_in, const int* in_sizes, int n_in,
                              void* d_out, int out_size) {
    const float* f1     = (const float*)d_in[0];   // [1024, 1024]
    const float* conv_w = (const float*)d_in[1];   // [1024, 1024, 16, 1]
    const float* conv_b = (const float*)d_in[2];   // [1024]
    float* out = (float*)d_out;                    // [1024, 2048]

    cudaFuncSetAttribute(hmma_gemm_kernel,
                         cudaFuncAttributeMaxDynamicSharedMemorySize, DSMEM_B);

    topk_kernel<<<NN, 1024>>>(f1);
    build_A_kernel<<<dim3(NPAIR, 64), 256>>>(f1);
    build_B_kernel<<<NN, 256>>>(conv_w);
    hmma_gemm_kernel<<<dim3(8, 16), 256, DSMEM_B>>>(conv_b, out);
    (void)in_sizes; (void)n_in; (void)out_size;
}